// round 14
// baseline (speedup 1.0000x reference)
#include <cuda_runtime.h>
#include <math.h>

// LearnableKalmanTracker.
//  Kernel 1 (riccati_kernel): batch-invariant covariance/gain recursion ->
//    PRE-PAIRED K table g_Kpair[t][q*4+j] = (K[q][j], K[q+4][j]) packed u64,
//    bitwise-exact early freeze (period-1/2).
//  Kernel 2 (consumer_kernel): affine-in-w step, packed f32x2 math.
//    R14 = R13 + pure deletions: sign-folded coefficients (G22/Bp/QG/C1
//    stored positive, evaluated with -w; removes 3 NEG mul2s), exact 0.5
//    fold of the tanh argument into W2 (removes one chain fma), and
//    clamp-free pointer-increment main loop with a 2-step epilogue.
// H_base = [I4|0] exploited analytically.

#define T_STEPS 512
#define FULLM 0xffffffffu

typedef unsigned long long u64p;

__device__ __align__(16) u64p g_Kpair[T_STEPS * 16];  // (K[q][j],K[q+4][j])

__device__ __forceinline__ u64p pk2(float lo, float hi) {
    u64p r; asm("mov.b64 %0, {%1, %2};" : "=l"(r) : "f"(lo), "f"(hi)); return r;
}
__device__ __forceinline__ void upk2(u64p v, float& lo, float& hi) {
    asm("mov.b64 {%0, %1}, %2;" : "=f"(lo), "=f"(hi) : "l"(v));
}
__device__ __forceinline__ u64p ffma2(u64p a, u64p b, u64p c) {
    u64p d; asm("fma.rn.f32x2 %0, %1, %2, %3;" : "=l"(d) : "l"(a), "l"(b), "l"(c)); return d;
}
__device__ __forceinline__ u64p fmul2(u64p a, u64p b) {
    u64p d; asm("mul.rn.f32x2 %0, %1, %2;" : "=l"(d) : "l"(a), "l"(b)); return d;
}
__device__ __forceinline__ u64p fadd2(u64p a, u64p b) {
    u64p d; asm("add.rn.f32x2 %0, %1, %2;" : "=l"(d) : "l"(a), "l"(b)); return d;
}
__device__ __forceinline__ float tanh_fast(float x) {
    float r; asm("tanh.approx.f32 %0, %1;" : "=f"(r) : "f"(x)); return r;
}

// ---------------- Kernel 1: shared Riccati recursion (32 threads) ----------
__global__ void __launch_bounds__(32)
riccati_kernel(const float* __restrict__ F_diag, const float* __restrict__ F_vel,
               const float* __restrict__ q_scale, const float* __restrict__ r_scale)
{
    __shared__ float C[64], P[64], Sinv[16], Ksh[32], fdv[8], fvv[4];
    const int lane = threadIdx.x;

    if (lane < 8) fdv[lane] = fminf(fmaxf(F_diag[lane], 0.9f), 1.1f);
    if (lane < 4) fvv[lane] = 1.0f / (1.0f + expf(-F_vel[lane]));
    const float qv = expf(q_scale[0]);
    const float rv = expf(r_scale[0]);

    const int e0 = lane, e1 = lane + 32;
    C[e0] = ((e0 >> 3) == (e0 & 7)) ? 1.0f : 0.0f;
    C[e1] = ((e1 >> 3) == (e1 & 7)) ? 1.0f : 0.0f;
    __syncwarp();

    float cold1_a = C[e0], cold1_b = C[e1];
    float cold2_a = 0.f,   cold2_b = 0.f;

    for (int t = 1; t < T_STEPS; ++t) {
#pragma unroll
        for (int h = 0; h < 2; h++) {
            int e = lane + h * 32;
            int i = e >> 3, j = e & 7;
            float fdi = fdv[i], fdj = fdv[j];
            float v = fdi * fdj * C[i * 8 + j];
            if (j < 4) v += fdi * fvv[j] * C[i * 8 + j + 4];
            if (i < 4) {
                float fvi = fvv[i];
                v += fvi * fdj * C[(i + 4) * 8 + j];
                if (j < 4) v += fvi * fvv[j] * C[(i + 4) * 8 + j + 4];
            }
            if (i == j) v += qv;
            P[e] = v;
        }
        __syncwarp();

        {
            int a = (lane >> 2) & 3, b = lane & 3;
            int r0 = 0 + (0 >= a), r1 = 1 + (1 >= a), r2 = 2 + (2 >= a);
            int c0 = 0 + (0 >= b), c1 = 1 + (1 >= b), c2 = 2 + (2 >= b);
            auto S = [&](int x, int y) -> float {
                float v = P[x * 8 + y];
                return (x == y) ? v + rv : v;
            };
            float m00 = S(r0, c0), m01 = S(r0, c1), m02 = S(r0, c2);
            float m10 = S(r1, c0), m11 = S(r1, c1), m12 = S(r1, c2);
            float m20 = S(r2, c0), m21 = S(r2, c1), m22 = S(r2, c2);
            float det3 = m00 * (m11 * m22 - m12 * m21)
                       - m01 * (m10 * m22 - m12 * m20)
                       + m02 * (m10 * m21 - m11 * m20);
            float cof = ((a + b) & 1) ? -det3 : det3;
            float c0v = __shfl_sync(FULLM, cof, 0);
            float c1v = __shfl_sync(FULLM, cof, 4);
            float c2v = __shfl_sync(FULLM, cof, 8);
            float c3v = __shfl_sync(FULLM, cof, 12);
            float det = S(0, 0) * c0v + S(1, 0) * c1v + S(2, 0) * c2v + S(3, 0) * c3v;
            float idet = __fdividef(1.0f, det);
            if (lane < 16) Sinv[b * 4 + a] = cof * idet;
        }
        __syncwarp();

        {
            int i = lane >> 2, m = lane & 3;
            float kv = P[i * 8 + 0] * Sinv[0 * 4 + m]
                     + P[i * 8 + 1] * Sinv[1 * 4 + m]
                     + P[i * 8 + 2] * Sinv[2 * 4 + m]
                     + P[i * 8 + 3] * Sinv[3 * 4 + m];
            Ksh[lane] = kv;
        }
        __syncwarp();

        if (lane < 16) {
            g_Kpair[t * 16 + lane] = pk2(Ksh[lane], Ksh[lane + 16]);
        }

        float na, nb;
        {
            int i0 = e0 >> 3, j0 = e0 & 7;
            float v = P[e0];
            v -= Ksh[i0 * 4 + 0] * P[0 * 8 + j0];
            v -= Ksh[i0 * 4 + 1] * P[1 * 8 + j0];
            v -= Ksh[i0 * 4 + 2] * P[2 * 8 + j0];
            v -= Ksh[i0 * 4 + 3] * P[3 * 8 + j0];
            na = v;
            int i1 = e1 >> 3, j1 = e1 & 7;
            float u = P[e1];
            u -= Ksh[i1 * 4 + 0] * P[0 * 8 + j1];
            u -= Ksh[i1 * 4 + 1] * P[1 * 8 + j1];
            u -= Ksh[i1 * 4 + 2] * P[2 * 8 + j1];
            u -= Ksh[i1 * 4 + 3] * P[3 * 8 + j1];
            nb = u;
        }
        int conv1 = __all_sync(FULLM, (na == cold1_a) && (nb == cold1_b));
        int conv2 = __all_sync(FULLM, (na == cold2_a) && (nb == cold2_b)) && (t >= 3);
        cold2_a = cold1_a; cold2_b = cold1_b;
        cold1_a = na;      cold1_b = nb;
        C[e0] = na; C[e1] = nb;
        __syncwarp();

        if (conv1) {
            if (lane < 16) {
                u64p kp = pk2(Ksh[lane], Ksh[lane + 16]);
                for (int u = t + 1; u < T_STEPS; ++u) g_Kpair[u * 16 + lane] = kp;
            }
            return;
        }
        if (conv2) {
            if (lane < 16) {
                u64p kA = pk2(Ksh[lane], Ksh[lane + 16]);
                u64p kB = g_Kpair[(t - 1) * 16 + lane];
                for (int u = t + 1; u < T_STEPS; ++u)
                    g_Kpair[u * 16 + lane] = ((u - t) & 1) ? kB : kA;
            }
            return;
        }
    }
}

// ---------------- Kernel 2: packed-f32x2 affine consumers ------------------

__device__ __forceinline__ float qsel(float4 v, int q) {
    float lo = (q & 1) ? v.y : v.x;
    float hi = (q & 1) ? v.w : v.z;
    return (q & 2) ? hi : lo;
}
// Depth-1 quad reduction: 3 parallel xor-shuffles + local tree (lane-identical).
__device__ __forceinline__ float qred(float v) {
    float a = __shfl_xor_sync(FULLM, v, 1, 4);
    float b = __shfl_xor_sync(FULLM, v, 2, 4);
    float c = __shfl_xor_sync(FULLM, v, 3, 4);
    return (v + a) + (b + c);
}

// One filter step. Sign conventions: G22p/Bp/QGp/C1p stored POSITIVE,
// evaluated with wn = -w. y accumulated with 0.5-folded W2 (exact).
#define STEP_BODY(ZF, KFA, KFB)                                               \
    {                                                                         \
        float4 zfut = (ZF);                                                   \
        ulonglong2 kfa = (KFA);                                               \
        ulonglong2 kfb = (KFB);                                               \
        /* ---- serial chain: w_s ---- */                                     \
        float wp = wprev, wnp = -wprev;                                       \
        u64p wp2 = pk2(wp, wp), wn2 = pk2(wnp, wnp);                          \
        float rstd = rsqrtf(fmaf(C2, wp * wp, fmaf(C1p, wnp, C0)));           \
        float t0, t1, t2, t3;                                                 \
        upk2(ffma2(QGp0, wn2, PGp0), t0, t1);                                 \
        upk2(ffma2(QGp1, wn2, PGp1), t2, t3);                                 \
        float n0 = fmaxf(fmaf(t0, rstd, bev[0]), 0.f) * w2h[0];               \
        float n1 = fmaxf(fmaf(t1, rstd, bev[1]), 0.f) * w2h[1];               \
        float n2 = fmaxf(fmaf(t2, rstd, bev[2]), 0.f) * w2h[2];               \
        float n3 = fmaxf(fmaf(t3, rstd, bev[3]), 0.f) * w2h[3];               \
        float y  = (n0 + n1) + (n2 + n3);                                     \
        float yA = __shfl_xor_sync(FULLM, y, 1, 4);                           \
        float yB = __shfl_xor_sync(FULLM, y, 2, 4);                           \
        float yC = __shfl_xor_sync(FULLM, y, 3, 4);                           \
        y = (y + yA) + (yB + yC);                                             \
        float th = tanh_fast(y + b2h);                                        \
        float w  = fmaf(smwh, th, smwh);                                      \
        /* ---- concrete state for step s ---- */                             \
        u64p p2   = ffma2(wp2, PB2, PA2);                                     \
        u64p kin2 = ffma2(wn2, G22p, G12);                                    \
        float pq, pq4, knq, knq4;                                             \
        upk2(p2, pq, pq4);                                                    \
        upk2(kin2, knq, knq4);                                                \
        *op = fmaf(w, knq, pq); op += 4;                                      \
        float tl, th2, ul, uh;                                                \
        upk2(fmul2(FD2, p2), tl, th2);                                        \
        float Fpq  = fmaf(fvq, pq4, tl);                                      \
        float Fpq4 = th2;                                                     \
        upk2(fmul2(FD2, kin2), ul, uh);                                       \
        float Fkq  = fmaf(fvq, knq4, ul);                                     \
        float Fkq4 = uh;                                                      \
        /* ---- quad broadcasts ---- */                                       \
        float zq = qsel(znext, q) - Fpq;                                      \
        float z0_ = __shfl_sync(FULLM, zq, 0, 4);                             \
        float z1_ = __shfl_sync(FULLM, zq, 1, 4);                             \
        float z2_ = __shfl_sync(FULLM, zq, 2, 4);                             \
        float z3_ = __shfl_sync(FULLM, zq, 3, 4);                             \
        float g0_ = __shfl_sync(FULLM, Fkq, 0, 4);                            \
        float g1_ = __shfl_sync(FULLM, Fkq, 1, 4);                            \
        float g2_ = __shfl_sync(FULLM, Fkq, 2, 4);                            \
        float g3_ = __shfl_sync(FULLM, Fkq, 3, 4);                            \
        u64p z0p = pk2(z0_, z0_), z1p = pk2(z1_, z1_);                        \
        u64p z2p = pk2(z2_, z2_), z3p = pk2(z3_, z3_);                        \
        u64p g0p = pk2(g0_, g0_), g1p = pk2(g1_, g1_);                        \
        u64p g2p = pk2(g2_, g2_), g3p = pk2(g3_, g3_);                        \
        /* ---- next-step coefficients (positive forms) ---- */               \
        u64p KP0 = kca.x, KP1 = kca.y, KP2 = kcb.x, KP3 = kcb.y;              \
        G12  = ffma2(KP3, z3p, ffma2(KP2, z2p, ffma2(KP1, z1p, fmul2(KP0, z0p)))); \
        G22p = ffma2(KP3, g3p, ffma2(KP2, g2p, ffma2(KP1, g1p, fmul2(KP0, g0p)))); \
        PA2 = pk2(Fpq, Fpq4);                                                 \
        PB2 = pk2(Fkq, Fkq4);                                                 \
        u64p zxp = pk2(znext.x, znext.x), zyp = pk2(znext.y, znext.y);        \
        u64p zzp = pk2(znext.z, znext.z), zwp = pk2(znext.w, znext.w);        \
        u64p Ap0 = ffma2(W1B0[3], zwp, ffma2(W1B0[2], zzp, ffma2(W1B0[1], zyp, ffma2(W1B0[0], zxp, B1p0)))); \
        Ap0 = ffma2(W1A0[3], z3p, ffma2(W1A0[2], z2p, ffma2(W1A0[1], z1p, ffma2(W1A0[0], z0p, Ap0)))); \
        u64p Ap1 = ffma2(W1B1[3], zwp, ffma2(W1B1[2], zzp, ffma2(W1B1[1], zyp, ffma2(W1B1[0], zxp, B1p1)))); \
        Ap1 = ffma2(W1A1[3], z3p, ffma2(W1A1[2], z2p, ffma2(W1A1[1], z1p, ffma2(W1A1[0], z0p, Ap1)))); \
        u64p Bp0 = ffma2(W1A0[3], g3p, ffma2(W1A0[2], g2p, ffma2(W1A0[1], g1p, fmul2(W1A0[0], g0p)))); \
        u64p Bp1 = ffma2(W1A1[3], g3p, ffma2(W1A1[2], g2p, ffma2(W1A1[1], g1p, fmul2(W1A1[0], g0p)))); \
        /* mean reductions then lane-local centered partials */               \
        float lo, hi;                                                         \
        float sa, sbp;                                                        \
        upk2(fadd2(Ap0, Ap1), lo, hi);  sa  = lo + hi;                        \
        upk2(fadd2(Bp0, Bp1), lo, hi);  sbp = lo + hi;                        \
        sa = qred(sa); sbp = qred(sbp);                                       \
        float mA = sa * 0.0625f, mBp = sbp * 0.0625f;                         \
        u64p mAn = pk2(-mA, -mA), mBpn = pk2(-mBp, -mBp);                     \
        u64p D0 = fadd2(Ap0, mAn),  D1 = fadd2(Ap1, mAn);                     \
        u64p E0 = fadd2(Bp0, mBpn), E1 = fadd2(Bp1, mBpn);                    \
        PGp0 = fmul2(D0, G1p0); PGp1 = fmul2(D1, G1p1);                       \
        QGp0 = fmul2(E0, G1p0); QGp1 = fmul2(E1, G1p1);                       \
        float c0L, c1L2, c2L;                                                 \
        upk2(ffma2(D1, D1, fmul2(D0, D0)), lo, hi); c0L = lo + hi;            \
        upk2(ffma2(D1, E1, fmul2(D0, E0)), lo, hi); c1L2 = 2.0f * (lo + hi);  \
        upk2(ffma2(E1, E1, fmul2(E0, E0)), lo, hi); c2L = lo + hi;            \
        float c0S = qred(c0L), c1S = qred(c1L2), c2S = qred(c2L);             \
        C0  = fmaf(c0S, 0.0625f, 1e-5f);                                      \
        C1p = c1S * 0.0625f;                                                  \
        C2  = c2S * 0.0625f;                                                  \
        znext = zfut; kca = kfa; kcb = kfb; wprev = w;                        \
    }

__global__ void __launch_bounds__(64, 1)
consumer_kernel(const float* __restrict__ meas,
                const float* __restrict__ F_diag,
                const float* __restrict__ F_vel,
                const float* __restrict__ mw,
                const float* __restrict__ W1,
                const float* __restrict__ b1,
                const float* __restrict__ g1,
                const float* __restrict__ be1,
                const float* __restrict__ W2,
                const float* __restrict__ b2,
                float* __restrict__ out)
{
    const int lane = threadIdx.x & 31;
    const int warp = threadIdx.x >> 5;
    const int q    = lane & 3;
    const int b    = blockIdx.x * 16 + warp * 8 + (lane >> 2);

    // lane-partitioned F: lane q owns state components q and q+4
    const float fdq  = fminf(fmaxf(F_diag[q], 0.9f), 1.1f);
    const float fdq4 = fminf(fmaxf(F_diag[q + 4], 0.9f), 1.1f);
    const float fvq  = 1.0f / (1.0f + expf(-F_vel[q]));
    const float smw  = 1.0f / (1.0f + expf(-mw[0]));
    const float smwh = 0.5f * smw;        // sigma(x)*smw = smwh + smwh*tanh(x/2)
    const float b2h  = 0.5f * b2[0];
    const u64p  FD2  = pk2(fdq, fdq4);

    // lane q owns hidden units 4q..4q+3; packed as pairs (0,1) and (2,3)
    u64p W1A0[4], W1A1[4], W1B0[4], W1B1[4];
    u64p B1p0, B1p1, G1p0, G1p1;
    float bev[4], w2h[4], g1s[4], b1s[4], w1as[4][4], w1bs[4][4];
#pragma unroll
    for (int k = 0; k < 4; k++) {
        int u = 4 * q + k;
#pragma unroll
        for (int j = 0; j < 4; j++) { w1as[k][j] = W1[u * 8 + j]; w1bs[k][j] = W1[u * 8 + 4 + j]; }
        b1s[k] = b1[u]; g1s[k] = g1[u]; bev[k] = be1[u];
        w2h[k] = 0.5f * W2[u];            // exact 0.5 fold for tanh argument
    }
#pragma unroll
    for (int j = 0; j < 4; j++) {
        W1A0[j] = pk2(w1as[0][j], w1as[1][j]);
        W1A1[j] = pk2(w1as[2][j], w1as[3][j]);
        W1B0[j] = pk2(w1bs[0][j], w1bs[1][j]);
        W1B1[j] = pk2(w1bs[2][j], w1bs[3][j]);
    }
    B1p0 = pk2(b1s[0], b1s[1]); B1p1 = pk2(b1s[2], b1s[3]);
    G1p0 = pk2(g1s[0], g1s[1]); G1p1 = pk2(g1s[2], g1s[3]);

    const float4* zr = (const float4*)(meas + (size_t)b * T_STEPS * 4);
    float* outp = out + (size_t)b * T_STEPS * 4;

    // ---- prologue: step-1 coefficient set (w-linear parts zero) ----
    float4 z0v = __ldg(&zr[0]);
    float4 z1v = __ldg(&zr[1]);
    float z0q = qsel(z0v, q);
    outp[q] = z0q;

    float PAq = fdq * z0q;
    float zfq = qsel(z1v, q) - PAq;
    float zf0 = __shfl_sync(FULLM, zfq, 0, 4);
    float zf1 = __shfl_sync(FULLM, zfq, 1, 4);
    float zf2 = __shfl_sync(FULLM, zfq, 2, 4);
    float zf3 = __shfl_sync(FULLM, zfq, 3, 4);

    u64p k10 = g_Kpair[16 + q * 4 + 0];
    u64p k11 = g_Kpair[16 + q * 4 + 1];
    u64p k12 = g_Kpair[16 + q * 4 + 2];
    u64p k13 = g_Kpair[16 + q * 4 + 3];
    u64p G12 = ffma2(k13, pk2(zf3, zf3), ffma2(k12, pk2(zf2, zf2),
               ffma2(k11, pk2(zf1, zf1), fmul2(k10, pk2(zf0, zf0)))));
    u64p G22p = pk2(0.f, 0.f);
    u64p PA2 = pk2(PAq, 0.f);
    u64p PB2 = pk2(0.f, 0.f);

    float Avs[4];
#pragma unroll
    for (int k = 0; k < 4; k++) {
        float a = fmaf(w1bs[k][0], z1v.x, b1s[k]);
        a = fmaf(w1bs[k][1], z1v.y, a);
        a = fmaf(w1bs[k][2], z1v.z, a);
        a = fmaf(w1bs[k][3], z1v.w, a);
        a = fmaf(w1as[k][0], zf0, a);
        a = fmaf(w1as[k][1], zf1, a);
        a = fmaf(w1as[k][2], zf2, a);
        a = fmaf(w1as[k][3], zf3, a);
        Avs[k] = a;
    }
    float C0, C1p = 0.f, C2 = 0.f;
    u64p PGp0, PGp1, QGp0 = pk2(0.f, 0.f), QGp1 = pk2(0.f, 0.f);
    {
        float sa = qred((Avs[0] + Avs[1]) + (Avs[2] + Avs[3]));
        float mA = sa * 0.0625f;
        float d0 = Avs[0] - mA, d1 = Avs[1] - mA;
        float d2 = Avs[2] - mA, d3 = Avs[3] - mA;
        float c0L = fmaf(d0, d0, fmaf(d1, d1, fmaf(d2, d2, d3 * d3)));
        C0 = fmaf(qred(c0L), 0.0625f, 1e-5f);
        PGp0 = pk2(d0 * g1s[0], d1 * g1s[1]);
        PGp1 = pk2(d2 * g1s[2], d3 * g1s[3]);
    }

    const ulonglong2* kp2 = (const ulonglong2*)(g_Kpair + 2 * 16 + q * 4);
    ulonglong2 kca = __ldg(kp2);
    ulonglong2 kcb = __ldg(kp2 + 1);
    float4 znext = __ldg(&zr[2]);
    float wprev = 0.f;
    float* op = outp + 4 + q;

    // pointer-increment prefetch streams (step s prefetches index s+2)
    const float4* zp = zr + 3;
    const ulonglong2* kfp = (const ulonglong2*)(g_Kpair + 3 * 16 + q * 4);

    // main loop: s = 1 .. 509 (prefetch index s+2 <= 511, clamp-free)
#pragma unroll 2
    for (int s = 1; s <= T_STEPS - 3; ++s) {
        STEP_BODY(__ldg(zp), __ldg(kfp), __ldg(kfp + 1));
        zp += 1; kfp += 8;
    }
    // epilogue: s = 510, 511 (prefetch clamped to last slot)
    {
        const float4* zpe = zr + (T_STEPS - 1);
        const ulonglong2* kpe = (const ulonglong2*)(g_Kpair + (T_STEPS - 1) * 16 + q * 4);
        STEP_BODY(__ldg(zpe), __ldg(kpe), __ldg(kpe + 1));
        STEP_BODY(__ldg(zpe), __ldg(kpe), __ldg(kpe + 1));
    }
}

extern "C" void kernel_launch(void* const* d_in, const int* in_sizes, int n_in,
                              void* d_out, int out_size) {
    const float* meas    = (const float*)d_in[0];
    const float* F_diag  = (const float*)d_in[1];
    const float* F_vel   = (const float*)d_in[2];
    // d_in[3] = H_base ([I4|0], exploited analytically)
    const float* q_scale = (const float*)d_in[4];
    const float* r_scale = (const float*)d_in[5];
    const float* mw      = (const float*)d_in[6];
    const float* W1      = (const float*)d_in[7];
    const float* b1      = (const float*)d_in[8];
    const float* g1      = (const float*)d_in[9];
    const float* be1     = (const float*)d_in[10];
    const float* W2      = (const float*)d_in[11];
    const float* b2      = (const float*)d_in[12];
    float* out = (float*)d_out;

    riccati_kernel<<<1, 32>>>(F_diag, F_vel, q_scale, r_scale);

    int B = in_sizes[0] / (T_STEPS * 4);           // 2048
    dim3 grid(B / 16);                             // 128 blocks x 2 warps, 8 seq/warp
    consumer_kernel<<<grid, 64>>>(
        meas, F_diag, F_vel, mw, W1, b1, g1, be1, W2, b2, out);
}

// round 15
// speedup vs baseline: 1.0333x; 1.0333x over previous
#include <cuda_runtime.h>
#include <math.h>

// LearnableKalmanTracker.
//  Kernel 1 (riccati_kernel): batch-invariant covariance/gain recursion ->
//    PRE-PAIRED K table g_Kpair[t][q*4+j] = (K[q][j], K[q+4][j]) packed u64,
//    bitwise-exact early freeze (period-1/2).
//  Kernel 2 (consumer_kernel): affine-in-w step, packed f32x2 math.
//    R15 = R13 body byte-identical + two micro-deletions only:
//      (1) exact 0.5-fold of the tanh argument into W2 (one chain fma gone),
//      (2) Horner form for the variance polynomial (one mul gone).
// H_base = [I4|0] exploited analytically.

#define T_STEPS 512
#define FULLM 0xffffffffu

typedef unsigned long long u64p;

__device__ __align__(16) u64p g_Kpair[T_STEPS * 16];  // (K[q][j],K[q+4][j])

__device__ __forceinline__ u64p pk2(float lo, float hi) {
    u64p r; asm("mov.b64 %0, {%1, %2};" : "=l"(r) : "f"(lo), "f"(hi)); return r;
}
__device__ __forceinline__ void upk2(u64p v, float& lo, float& hi) {
    asm("mov.b64 {%0, %1}, %2;" : "=f"(lo), "=f"(hi) : "l"(v));
}
__device__ __forceinline__ u64p ffma2(u64p a, u64p b, u64p c) {
    u64p d; asm("fma.rn.f32x2 %0, %1, %2, %3;" : "=l"(d) : "l"(a), "l"(b), "l"(c)); return d;
}
__device__ __forceinline__ u64p fmul2(u64p a, u64p b) {
    u64p d; asm("mul.rn.f32x2 %0, %1, %2;" : "=l"(d) : "l"(a), "l"(b)); return d;
}
__device__ __forceinline__ u64p fadd2(u64p a, u64p b) {
    u64p d; asm("add.rn.f32x2 %0, %1, %2;" : "=l"(d) : "l"(a), "l"(b)); return d;
}
__device__ __forceinline__ float tanh_fast(float x) {
    float r; asm("tanh.approx.f32 %0, %1;" : "=f"(r) : "f"(x)); return r;
}

// ---------------- Kernel 1: shared Riccati recursion (32 threads) ----------
__global__ void __launch_bounds__(32)
riccati_kernel(const float* __restrict__ F_diag, const float* __restrict__ F_vel,
               const float* __restrict__ q_scale, const float* __restrict__ r_scale)
{
    __shared__ float C[64], P[64], Sinv[16], Ksh[32], fdv[8], fvv[4];
    const int lane = threadIdx.x;

    if (lane < 8) fdv[lane] = fminf(fmaxf(F_diag[lane], 0.9f), 1.1f);
    if (lane < 4) fvv[lane] = 1.0f / (1.0f + expf(-F_vel[lane]));
    const float qv = expf(q_scale[0]);
    const float rv = expf(r_scale[0]);

    const int e0 = lane, e1 = lane + 32;
    C[e0] = ((e0 >> 3) == (e0 & 7)) ? 1.0f : 0.0f;
    C[e1] = ((e1 >> 3) == (e1 & 7)) ? 1.0f : 0.0f;
    __syncwarp();

    float cold1_a = C[e0], cold1_b = C[e1];
    float cold2_a = 0.f,   cold2_b = 0.f;

    for (int t = 1; t < T_STEPS; ++t) {
#pragma unroll
        for (int h = 0; h < 2; h++) {
            int e = lane + h * 32;
            int i = e >> 3, j = e & 7;
            float fdi = fdv[i], fdj = fdv[j];
            float v = fdi * fdj * C[i * 8 + j];
            if (j < 4) v += fdi * fvv[j] * C[i * 8 + j + 4];
            if (i < 4) {
                float fvi = fvv[i];
                v += fvi * fdj * C[(i + 4) * 8 + j];
                if (j < 4) v += fvi * fvv[j] * C[(i + 4) * 8 + j + 4];
            }
            if (i == j) v += qv;
            P[e] = v;
        }
        __syncwarp();

        {
            int a = (lane >> 2) & 3, b = lane & 3;
            int r0 = 0 + (0 >= a), r1 = 1 + (1 >= a), r2 = 2 + (2 >= a);
            int c0 = 0 + (0 >= b), c1 = 1 + (1 >= b), c2 = 2 + (2 >= b);
            auto S = [&](int x, int y) -> float {
                float v = P[x * 8 + y];
                return (x == y) ? v + rv : v;
            };
            float m00 = S(r0, c0), m01 = S(r0, c1), m02 = S(r0, c2);
            float m10 = S(r1, c0), m11 = S(r1, c1), m12 = S(r1, c2);
            float m20 = S(r2, c0), m21 = S(r2, c1), m22 = S(r2, c2);
            float det3 = m00 * (m11 * m22 - m12 * m21)
                       - m01 * (m10 * m22 - m12 * m20)
                       + m02 * (m10 * m21 - m11 * m20);
            float cof = ((a + b) & 1) ? -det3 : det3;
            float c0v = __shfl_sync(FULLM, cof, 0);
            float c1v = __shfl_sync(FULLM, cof, 4);
            float c2v = __shfl_sync(FULLM, cof, 8);
            float c3v = __shfl_sync(FULLM, cof, 12);
            float det = S(0, 0) * c0v + S(1, 0) * c1v + S(2, 0) * c2v + S(3, 0) * c3v;
            float idet = __fdividef(1.0f, det);
            if (lane < 16) Sinv[b * 4 + a] = cof * idet;
        }
        __syncwarp();

        {
            int i = lane >> 2, m = lane & 3;
            float kv = P[i * 8 + 0] * Sinv[0 * 4 + m]
                     + P[i * 8 + 1] * Sinv[1 * 4 + m]
                     + P[i * 8 + 2] * Sinv[2 * 4 + m]
                     + P[i * 8 + 3] * Sinv[3 * 4 + m];
            Ksh[lane] = kv;
        }
        __syncwarp();

        if (lane < 16) {
            g_Kpair[t * 16 + lane] = pk2(Ksh[lane], Ksh[lane + 16]);
        }

        float na, nb;
        {
            int i0 = e0 >> 3, j0 = e0 & 7;
            float v = P[e0];
            v -= Ksh[i0 * 4 + 0] * P[0 * 8 + j0];
            v -= Ksh[i0 * 4 + 1] * P[1 * 8 + j0];
            v -= Ksh[i0 * 4 + 2] * P[2 * 8 + j0];
            v -= Ksh[i0 * 4 + 3] * P[3 * 8 + j0];
            na = v;
            int i1 = e1 >> 3, j1 = e1 & 7;
            float u = P[e1];
            u -= Ksh[i1 * 4 + 0] * P[0 * 8 + j1];
            u -= Ksh[i1 * 4 + 1] * P[1 * 8 + j1];
            u -= Ksh[i1 * 4 + 2] * P[2 * 8 + j1];
            u -= Ksh[i1 * 4 + 3] * P[3 * 8 + j1];
            nb = u;
        }
        int conv1 = __all_sync(FULLM, (na == cold1_a) && (nb == cold1_b));
        int conv2 = __all_sync(FULLM, (na == cold2_a) && (nb == cold2_b)) && (t >= 3);
        cold2_a = cold1_a; cold2_b = cold1_b;
        cold1_a = na;      cold1_b = nb;
        C[e0] = na; C[e1] = nb;
        __syncwarp();

        if (conv1) {
            if (lane < 16) {
                u64p kp = pk2(Ksh[lane], Ksh[lane + 16]);
                for (int u = t + 1; u < T_STEPS; ++u) g_Kpair[u * 16 + lane] = kp;
            }
            return;
        }
        if (conv2) {
            if (lane < 16) {
                u64p kA = pk2(Ksh[lane], Ksh[lane + 16]);
                u64p kB = g_Kpair[(t - 1) * 16 + lane];
                for (int u = t + 1; u < T_STEPS; ++u)
                    g_Kpair[u * 16 + lane] = ((u - t) & 1) ? kB : kA;
            }
            return;
        }
    }
}

// ---------------- Kernel 2: packed-f32x2 affine consumers ------------------

__device__ __forceinline__ float qsel(float4 v, int q) {
    float lo = (q & 1) ? v.y : v.x;
    float hi = (q & 1) ? v.w : v.z;
    return (q & 2) ? hi : lo;
}
// Depth-1 quad reduction: 3 parallel xor-shuffles + local tree (lane-identical).
__device__ __forceinline__ float qred(float v) {
    float a = __shfl_xor_sync(FULLM, v, 1, 4);
    float b = __shfl_xor_sync(FULLM, v, 2, 4);
    float c = __shfl_xor_sync(FULLM, v, 3, 4);
    return (v + a) + (b + c);
}

__global__ void __launch_bounds__(64, 1)
consumer_kernel(const float* __restrict__ meas,
                const float* __restrict__ F_diag,
                const float* __restrict__ F_vel,
                const float* __restrict__ mw,
                const float* __restrict__ W1,
                const float* __restrict__ b1,
                const float* __restrict__ g1,
                const float* __restrict__ be1,
                const float* __restrict__ W2,
                const float* __restrict__ b2,
                float* __restrict__ out)
{
    const int lane = threadIdx.x & 31;
    const int warp = threadIdx.x >> 5;
    const int q    = lane & 3;
    const int b    = blockIdx.x * 16 + warp * 8 + (lane >> 2);

    // lane-partitioned F: lane q owns state components q and q+4
    const float fdq  = fminf(fmaxf(F_diag[q], 0.9f), 1.1f);
    const float fdq4 = fminf(fmaxf(F_diag[q + 4], 0.9f), 1.1f);
    const float fvq  = 1.0f / (1.0f + expf(-F_vel[q]));
    const float smw  = 1.0f / (1.0f + expf(-mw[0]));
    const float smwh = 0.5f * smw;        // sigma(x)*smw = smwh + smwh*tanh(x/2)
    const float b2h  = 0.5f * b2[0];
    const u64p  FD2  = pk2(fdq, fdq4);
    const u64p  NEG2 = pk2(-1.0f, -1.0f);

    // lane q owns hidden units 4q..4q+3; packed as pairs (0,1) and (2,3)
    u64p W1A0[4], W1A1[4], W1B0[4], W1B1[4];
    u64p B1p0, B1p1, G1p0, G1p1;
    float bev[4], w2h[4], g1s[4], b1s[4], w1as[4][4], w1bs[4][4];
#pragma unroll
    for (int k = 0; k < 4; k++) {
        int u = 4 * q + k;
#pragma unroll
        for (int j = 0; j < 4; j++) { w1as[k][j] = W1[u * 8 + j]; w1bs[k][j] = W1[u * 8 + 4 + j]; }
        b1s[k] = b1[u]; g1s[k] = g1[u]; bev[k] = be1[u];
        w2h[k] = 0.5f * W2[u];            // exact 0.5 fold (tanh argument)
    }
#pragma unroll
    for (int j = 0; j < 4; j++) {
        W1A0[j] = pk2(w1as[0][j], w1as[1][j]);
        W1A1[j] = pk2(w1as[2][j], w1as[3][j]);
        W1B0[j] = pk2(w1bs[0][j], w1bs[1][j]);
        W1B1[j] = pk2(w1bs[2][j], w1bs[3][j]);
    }
    B1p0 = pk2(b1s[0], b1s[1]); B1p1 = pk2(b1s[2], b1s[3]);
    G1p0 = pk2(g1s[0], g1s[1]); G1p1 = pk2(g1s[2], g1s[3]);

    const float4* zr = (const float4*)(meas + (size_t)b * T_STEPS * 4);
    float* outp = out + (size_t)b * T_STEPS * 4;

    // ---- prologue: step-1 coefficient set (w-linear parts zero) ----
    float4 z0v = __ldg(&zr[0]);
    float4 z1v = __ldg(&zr[1]);
    float z0q = qsel(z0v, q);
    outp[q] = z0q;

    float PAq = fdq * z0q;
    float zfq = qsel(z1v, q) - PAq;
    float zf0 = __shfl_sync(FULLM, zfq, 0, 4);
    float zf1 = __shfl_sync(FULLM, zfq, 1, 4);
    float zf2 = __shfl_sync(FULLM, zfq, 2, 4);
    float zf3 = __shfl_sync(FULLM, zfq, 3, 4);

    u64p k10 = g_Kpair[16 + q * 4 + 0];
    u64p k11 = g_Kpair[16 + q * 4 + 1];
    u64p k12 = g_Kpair[16 + q * 4 + 2];
    u64p k13 = g_Kpair[16 + q * 4 + 3];
    u64p G12 = ffma2(k13, pk2(zf3, zf3), ffma2(k12, pk2(zf2, zf2),
               ffma2(k11, pk2(zf1, zf1), fmul2(k10, pk2(zf0, zf0)))));
    u64p G22 = pk2(0.f, 0.f);
    u64p PA2 = pk2(PAq, 0.f);
    u64p PB2 = pk2(0.f, 0.f);

    float Avs[4];
#pragma unroll
    for (int k = 0; k < 4; k++) {
        float a = fmaf(w1bs[k][0], z1v.x, b1s[k]);
        a = fmaf(w1bs[k][1], z1v.y, a);
        a = fmaf(w1bs[k][2], z1v.z, a);
        a = fmaf(w1bs[k][3], z1v.w, a);
        a = fmaf(w1as[k][0], zf0, a);
        a = fmaf(w1as[k][1], zf1, a);
        a = fmaf(w1as[k][2], zf2, a);
        a = fmaf(w1as[k][3], zf3, a);
        Avs[k] = a;
    }
    float C0, C1 = 0.f, C2 = 0.f;
    u64p PGp0, PGp1, QGp0 = pk2(0.f, 0.f), QGp1 = pk2(0.f, 0.f);
    {
        float sa = qred((Avs[0] + Avs[1]) + (Avs[2] + Avs[3]));
        float mA = sa * 0.0625f;
        float d0 = Avs[0] - mA, d1 = Avs[1] - mA;
        float d2 = Avs[2] - mA, d3 = Avs[3] - mA;
        float c0L = fmaf(d0, d0, fmaf(d1, d1, fmaf(d2, d2, d3 * d3)));
        C0 = fmaf(qred(c0L), 0.0625f, 1e-5f);
        PGp0 = pk2(d0 * g1s[0], d1 * g1s[1]);
        PGp1 = pk2(d2 * g1s[2], d3 * g1s[3]);
    }

    const ulonglong2* kp2 = (const ulonglong2*)(g_Kpair + 2 * 16 + q * 4);
    ulonglong2 kca = __ldg(kp2);
    ulonglong2 kcb = __ldg(kp2 + 1);
    float4 znext = __ldg(&zr[2]);
    float wprev = 0.f;
    float* op = outp + 4 + q;

#pragma unroll 2
    for (int s = 1; s < T_STEPS; ++s) {
        int fi = min(s + 2, T_STEPS - 1);
        float4 zfut = __ldg(&zr[fi]);
        const ulonglong2* kfp = (const ulonglong2*)(g_Kpair + (size_t)fi * 16 + q * 4);
        ulonglong2 kfa = __ldg(kfp);
        ulonglong2 kfb = __ldg(kfp + 1);

        // ======== serial chain: w_s from wprev + coefficient set ========
        float wp  = wprev;
        u64p wp2  = pk2(wp, wp);
        float rstd = rsqrtf(fmaf(wp, fmaf(wp, C2, C1), C0));  // Horner, +eps in C0
        float t0, t1, t2, t3;
        upk2(ffma2(QGp0, wp2, PGp0), t0, t1);
        upk2(ffma2(QGp1, wp2, PGp1), t2, t3);
        float n0 = fmaxf(fmaf(t0, rstd, bev[0]), 0.f) * w2h[0];
        float n1 = fmaxf(fmaf(t1, rstd, bev[1]), 0.f) * w2h[1];
        float n2 = fmaxf(fmaf(t2, rstd, bev[2]), 0.f) * w2h[2];
        float n3 = fmaxf(fmaf(t3, rstd, bev[3]), 0.f) * w2h[3];
        float y  = (n0 + n1) + (n2 + n3);
        float yA = __shfl_xor_sync(FULLM, y, 1, 4);
        float yB = __shfl_xor_sync(FULLM, y, 2, 4);
        float yC = __shfl_xor_sync(FULLM, y, 3, 4);
        y = (y + yA) + (yB + yC);
        float th = tanh_fast(y + b2h);
        float w  = fmaf(smwh, th, smwh);                           // w_s

        // ======== concrete state for step s (packed) ========
        u64p p2   = ffma2(wp2, PB2, PA2);
        u64p kin2 = ffma2(wp2, G22, G12);
        float pq, pq4, knq, knq4;
        upk2(p2, pq, pq4);
        upk2(kin2, knq, knq4);
        *op = fmaf(w, knq, pq); op += 4;

        float tl, th2, ul, uh;
        upk2(fmul2(FD2, p2), tl, th2);
        float Fpq  = fmaf(fvq, pq4, tl);
        float Fpq4 = th2;
        upk2(fmul2(FD2, kin2), ul, uh);
        float Fkq  = fmaf(fvq, knq4, ul);
        float Fkq4 = uh;

        // ======== quad broadcasts ========
        float zq = qsel(znext, q) - Fpq;
        float z0_ = __shfl_sync(FULLM, zq, 0, 4);
        float z1_ = __shfl_sync(FULLM, zq, 1, 4);
        float z2_ = __shfl_sync(FULLM, zq, 2, 4);
        float z3_ = __shfl_sync(FULLM, zq, 3, 4);
        float g0_ = __shfl_sync(FULLM, Fkq, 0, 4);
        float g1_ = __shfl_sync(FULLM, Fkq, 1, 4);
        float g2_ = __shfl_sync(FULLM, Fkq, 2, 4);
        float g3_ = __shfl_sync(FULLM, Fkq, 3, 4);

        u64p z0p = pk2(z0_, z0_), z1p = pk2(z1_, z1_);
        u64p z2p = pk2(z2_, z2_), z3p = pk2(z3_, z3_);
        u64p g0p = pk2(g0_, g0_), g1p = pk2(g1_, g1_);
        u64p g2p = pk2(g2_, g2_), g3p = pk2(g3_, g3_);

        // ======== next-step coefficients (K pairs pre-transposed) ========
        u64p KP0 = kca.x, KP1 = kca.y, KP2 = kcb.x, KP3 = kcb.y;
        G12 = ffma2(KP3, z3p, ffma2(KP2, z2p, ffma2(KP1, z1p, fmul2(KP0, z0p))));
        G22 = fmul2(ffma2(KP3, g3p, ffma2(KP2, g2p, ffma2(KP1, g1p, fmul2(KP0, g0p)))), NEG2);
        PA2 = pk2(Fpq, Fpq4);
        PB2 = pk2(Fkq, Fkq4);

        u64p zxp = pk2(znext.x, znext.x), zyp = pk2(znext.y, znext.y);
        u64p zzp = pk2(znext.z, znext.z), zwp = pk2(znext.w, znext.w);

        u64p Ap0 = ffma2(W1B0[3], zwp, ffma2(W1B0[2], zzp, ffma2(W1B0[1], zyp, ffma2(W1B0[0], zxp, B1p0))));
        Ap0 = ffma2(W1A0[3], z3p, ffma2(W1A0[2], z2p, ffma2(W1A0[1], z1p, ffma2(W1A0[0], z0p, Ap0))));
        u64p Ap1 = ffma2(W1B1[3], zwp, ffma2(W1B1[2], zzp, ffma2(W1B1[1], zyp, ffma2(W1B1[0], zxp, B1p1))));
        Ap1 = ffma2(W1A1[3], z3p, ffma2(W1A1[2], z2p, ffma2(W1A1[1], z1p, ffma2(W1A1[0], z0p, Ap1))));

        u64p Bp0 = fmul2(ffma2(W1A0[3], g3p, ffma2(W1A0[2], g2p,
                         ffma2(W1A0[1], g1p, fmul2(W1A0[0], g0p)))), NEG2);
        u64p Bp1 = fmul2(ffma2(W1A1[3], g3p, ffma2(W1A1[2], g2p,
                         ffma2(W1A1[1], g1p, fmul2(W1A1[0], g0p)))), NEG2);

        // mean reductions (2 qreds) then lane-local centered partials
        float lo, hi;
        float sa, sb;
        upk2(fadd2(Ap0, Ap1), lo, hi);  sa = lo + hi;
        upk2(fadd2(Bp0, Bp1), lo, hi);  sb = lo + hi;
        sa = qred(sa); sb = qred(sb);
        float mA = sa * 0.0625f, mB = sb * 0.0625f;

        u64p mAn = pk2(-mA, -mA), mBn = pk2(-mB, -mB);
        u64p D0 = fadd2(Ap0, mAn), D1 = fadd2(Ap1, mAn);
        u64p E0 = fadd2(Bp0, mBn), E1 = fadd2(Bp1, mBn);
        PGp0 = fmul2(D0, G1p0); PGp1 = fmul2(D1, G1p1);
        QGp0 = fmul2(E0, G1p0); QGp1 = fmul2(E1, G1p1);

        // centered coefficient partials, reduced OFF-CHAIN
        float c0L, c1L2, c2L;
        upk2(ffma2(D1, D1, fmul2(D0, D0)), lo, hi); c0L = lo + hi;
        upk2(ffma2(D1, E1, fmul2(D0, E0)), lo, hi); c1L2 = 2.0f * (lo + hi);
        upk2(ffma2(E1, E1, fmul2(E0, E0)), lo, hi); c2L = lo + hi;
        float c0S = qred(c0L), c1S = qred(c1L2), c2S = qred(c2L);
        C0 = fmaf(c0S, 0.0625f, 1e-5f);
        C1 = c1S * 0.0625f;
        C2 = c2S * 0.0625f;

        znext = zfut; kca = kfa; kcb = kfb; wprev = w;
    }
}

extern "C" void kernel_launch(void* const* d_in, const int* in_sizes, int n_in,
                              void* d_out, int out_size) {
    const float* meas    = (const float*)d_in[0];
    const float* F_diag  = (const float*)d_in[1];
    const float* F_vel   = (const float*)d_in[2];
    // d_in[3] = H_base ([I4|0], exploited analytically)
    const float* q_scale = (const float*)d_in[4];
    const float* r_scale = (const float*)d_in[5];
    const float* mw      = (const float*)d_in[6];
    const float* W1      = (const float*)d_in[7];
    const float* b1      = (const float*)d_in[8];
    const float* g1      = (const float*)d_in[9];
    const float* be1     = (const float*)d_in[10];
    const float* W2      = (const float*)d_in[11];
    const float* b2      = (const float*)d_in[12];
    float* out = (float*)d_out;

    riccati_kernel<<<1, 32>>>(F_diag, F_vel, q_scale, r_scale);

    int B = in_sizes[0] / (T_STEPS * 4);           // 2048
    dim3 grid(B / 16);                             // 128 blocks x 2 warps, 8 seq/warp
    consumer_kernel<<<grid, 64>>>(
        meas, F_diag, F_vel, mw, W1, b1, g1, be1, W2, b2, out);
}